// round 12
// baseline (speedup 1.0000x reference)
#include <cuda_runtime.h>
#include <cuda_bf16.h>
#include <cstdint>

// ---------------- output layout (float32 concat, reference return order) ---
#define OFF_Q     0u
#define OFF_LOSS  4194304u
#define OFF_PERP  4194368u
#define OFF_ENC   4194369u
#define OFF_EIDX  37748801u
#define OFF_DIST  37814337u

// ---------------- dynamic SMEM layout (bytes) ------------------------------
#define PB 144                          // 72 bf16 pitch: ldmatrix conflict-free
#define S_WHI   0                       // 512 x 72 bf16 hi      73728
#define S_XHI   73728                   // 128 x 72 bf16 hi      18432
#define S_XLO   92160                   // 128 x 72 bf16 lo      18432
#define S_XRAW0 110592                  // raw x tile buf0       32768
#define S_XRAW1 143360                  // raw x tile buf1       32768
#define S_EE    176128                  // 512 f32                2048
#define S_XXP   178176                  // 4 x 128 f32            2048
#define S_IDX   180224                  // 128 int                 512
#define S_LRED  180736                  // 16 f32                   64
#define S_CD1   180800                  // [2][128] f32           1024
#define S_CD2   181824
#define S_CD3   182848
#define S_CK1   183872                  // [2][128] int           1024
#define S_CK2   184896
#define S_CK3   185920
#define S_TKT   186944                  // ticket broadcast         16
#define S_STG   186960                  // 16 warps x 16 x 34 f32 34816
#define S_TOTAL 221776                  // <= 232448
// q_out staging (128 x 66 f32 = 33792 B) reuses S_STG after dist writes.

// ---------------- scratch (allocation-free, self-resetting) ----------------
__device__ unsigned int        g_cnt[512];     // histogram
__device__ unsigned long long  g_loss_i[64];   // fixed-point loss partials
__device__ unsigned int        g_tick;         // CTA completion ticket
__device__ unsigned int        g_tile;         // work-stealing tile counter

// ---------------- asm helpers ----------------------------------------------
__device__ __forceinline__ uint32_t smem_u32(const void* p) {
    uint32_t a;
    asm("{ .reg .u64 t; cvta.to.shared.u64 t, %1; cvt.u32.u64 %0, t; }" : "=r"(a) : "l"(p));
    return a;
}
#define LDSM_X4(r, a)                                                          \
    asm volatile("ldmatrix.sync.aligned.m8n8.x4.shared.b16 {%0,%1,%2,%3}, [%4];" \
        : "=r"((r)[0]), "=r"((r)[1]), "=r"((r)[2]), "=r"((r)[3]) : "r"(a))

#define MMA16816(d, a, b)                                                      \
    asm volatile("mma.sync.aligned.m16n8k16.row.col.f32.bf16.bf16.f32 "        \
        "{%0,%1,%2,%3}, {%4,%5,%6,%7}, {%8,%9}, {%0,%1,%2,%3};"                \
        : "+f"((d)[0]), "+f"((d)[1]), "+f"((d)[2]), "+f"((d)[3])               \
        : "r"((a)[0]), "r"((a)[1]), "r"((a)[2]), "r"((a)[3]),                  \
          "r"((b)[0]), "r"((b)[1]))

#define CP_ASYNC16(dst, src)                                                   \
    asm volatile("cp.async.cg.shared.global [%0], [%1], 16;" :: "r"(dst), "l"(src))
#define CP_COMMIT  asm volatile("cp.async.commit_group;")
#define CP_WAIT0   asm volatile("cp.async.wait_group 0;" ::: "memory")

__device__ __forceinline__ unsigned short f2bf(float v) {
    __nv_bfloat16 b = __float2bfloat16_rn(v);
    return *reinterpret_cast<unsigned short*>(&b);
}
__device__ __forceinline__ float bf2f(unsigned short u) {
    __nv_bfloat16 b = *reinterpret_cast<__nv_bfloat16*>(&u);
    return __bfloat162float(b);
}
__device__ __forceinline__ uint32_t pack_hi(float a, float b) {
    return (uint32_t)f2bf(a) | ((uint32_t)f2bf(b) << 16);
}
__device__ __forceinline__ uint32_t pack_lo(float a, float b) {
    return (uint32_t)f2bf(a - bf2f(f2bf(a))) | ((uint32_t)f2bf(b - bf2f(f2bf(b))) << 16);
}

__device__ __forceinline__ bool lessk(float e, int j, float d, int k) {
    return e < d || (e == d && j < k);
}
__device__ __forceinline__ void top3_upd(float d, int k, float& d1, int& k1,
                                         float& d2, int& k2, float& d3, int& k3) {
    if (d < d1)      { d3 = d2; k3 = k2; d2 = d1; k2 = k1; d1 = d; k1 = k; }
    else if (d < d2) { d3 = d2; k3 = k2; d2 = d; k2 = k; }
    else if (d < d3) { d3 = d; k3 = k; }
}
__device__ __forceinline__ void top3_ins(float e, int j, float& d1, int& k1,
                                         float& d2, int& k2, float& d3, int& k3) {
    if (lessk(e, j, d1, k1))      { d3 = d2; k3 = k2; d2 = d1; k2 = k1; d1 = e; k1 = j; }
    else if (lessk(e, j, d2, k2)) { d3 = d2; k3 = k2; d2 = e; k2 = j; }
    else if (lessk(e, j, d3, k3)) { d3 = e; k3 = j; }
}
__device__ __forceinline__ float dot_exact(const float* xr, const float* wr) {
    float s = 0.f;
#pragma unroll
    for (int c = 0; c < 64; ++c) s = fmaf(xr[(size_t)c * 1024], wr[c], s);
    return s;
}

// raw x tile prefetch: 64 channels x 128 hw floats, smem layout [c][hwl]
__device__ __forceinline__ void prefetch_x(uint32_t sraw, const float* x,
                                           int tile, int t) {
    const int bb = tile >> 3, hw0 = (tile & 7) << 7;
    const float* base = x + (size_t)bb * 65536 + hw0;
#pragma unroll
    for (int q = 0; q < 4; ++q) {
        const int ch = t + 512 * q;          // 0..2047
        const int c = ch >> 5, j = ch & 31;
        CP_ASYNC16(sraw + c * 512 + j * 16, base + (size_t)c * 1024 + j * 4);
    }
}

// ===========================================================================
// Persistent fused kernel: 148 CTAs x 512 thr. Codebook converted once per
// CTA; tiles (128 rows each) pulled via global ticket; x double-buffered via
// cp.async. HMMA bf16 2-pass (x hi/lo vs w hi). Top-3 + exact fp32 fixup.
// ===========================================================================
__global__ void __launch_bounds__(512, 1)
k_main(const float* __restrict__ x, const float* __restrict__ w,
       float* __restrict__ out) {
    extern __shared__ char sm[];
    const uint32_t su = smem_u32(sm);
    const int t    = threadIdx.x;
    const int lane = t & 31;
    const int wid  = t >> 5;

    // ---- prolog: w -> bf16 hi pitched; ee[k] = ||w_k||^2 (ONCE) -----------
    {
        const float4* w4 = (const float4*)w;
#pragma unroll
        for (int it = 0; it < 16; ++it) {
            const int u = t + 512 * it;
            const int k = u >> 4, j = u & 15;          // 16 threads per code
            float4 v = w4[(size_t)k * 16 + j];
            float s = v.x * v.x + v.y * v.y + v.z * v.z + v.w * v.w;
            s += __shfl_xor_sync(0xffffffffu, s, 8);
            s += __shfl_xor_sync(0xffffffffu, s, 4);
            s += __shfl_xor_sync(0xffffffffu, s, 2);
            s += __shfl_xor_sync(0xffffffffu, s, 1);
            if ((t & 15) == 0) ((float*)(sm + S_EE))[k] = s;
            *(uint2*)(sm + S_WHI + k * PB + j * 8) =
                make_uint2(pack_hi(v.x, v.y), pack_hi(v.z, v.w));
        }
    }

    // ---- first ticket + first prefetch ------------------------------------
    if (t == 0) *(int*)(sm + S_TKT) = (int)atomicAdd(&g_tile, 1u);
    __syncthreads();
    int tile = *(const int*)(sm + S_TKT);
    if (tile < 512) prefetch_x(su + S_XRAW0, x, tile, t);
    CP_COMMIT;
    int buf = 0;

    // loop-invariant lane decompositions
    const int wg = wid >> 1, h = wid & 1;
    const int r0 = wg * 16;
    const int l7 = lane & 7, seg = lane >> 3, t4 = lane & 3, g = lane >> 2;
    const uint32_t aoff = (uint32_t)(r0 + l7 + ((seg & 1) << 3)) * PB + ((seg >> 1) << 4);
    const uint32_t boff = (uint32_t)(l7 + ((seg >> 1) << 3)) * PB + ((seg & 1) << 4);
    const float* ee  = (const float*)(sm + S_EE);
    const float* xxp = (const float*)(sm + S_XXP);
    float* stg = (float*)(sm + S_STG) + wid * (16 * 34);

    while (tile < 512) {
        const int n0  = tile << 7;
        const int bb  = tile >> 3;
        const int hw0 = (tile & 7) << 7;

        if (t == 0) *(int*)(sm + S_TKT) = (int)atomicAdd(&g_tile, 1u);
        CP_WAIT0;
        __syncthreads();                       // raw[buf] ready; ticket visible
        const int ntile = *(const int*)(sm + S_TKT);
        if (ntile < 512)
            prefetch_x(su + S_XRAW0 + ((buf ^ 1) << 15), x, ntile, t);
        CP_COMMIT;

        // ---- convert raw x -> bf16 hi/lo + 4-way ||x||^2 partials ---------
        {
            const float* raw = (const float*)(sm + S_XRAW0 + (buf << 15));
            const int hwl = t & 127, ch4 = t >> 7;
            float xxa = 0.f;
#pragma unroll
            for (int cc = 0; cc < 16; cc += 2) {
                const int c = ch4 * 16 + cc;
                float v0 = raw[c * 128 + hwl];
                float v1 = raw[(c + 1) * 128 + hwl];
                xxa = fmaf(v0, v0, fmaf(v1, v1, xxa));
                *(uint32_t*)(sm + S_XHI + hwl * PB + c * 2) = pack_hi(v0, v1);
                *(uint32_t*)(sm + S_XLO + hwl * PB + c * 2) = pack_lo(v0, v1);
            }
            ((float*)(sm + S_XXP))[ch4 * 128 + hwl] = xxa;
        }
        __syncthreads();

        // ---- A fragments (hi + lo) ----------------------------------------
        uint32_t AH[4][4], AL[4][4];
#pragma unroll
        for (int kk = 0; kk < 4; ++kk) {
            LDSM_X4(AH[kk], su + S_XHI + aoff + kk * 32);
            LDSM_X4(AL[kk], su + S_XLO + aoff + kk * 32);
        }
        const float xg0 = xxp[r0 + g]       + xxp[128 + r0 + g]
                        + xxp[256 + r0 + g] + xxp[384 + r0 + g];
        const float xg8 = xxp[r0 + g + 8]       + xxp[128 + r0 + g + 8]
                        + xxp[256 + r0 + g + 8] + xxp[384 + r0 + g + 8];

        float d1 = 3.4e38f, d2 = 3.4e38f, d3 = 3.4e38f;       // row g
        int   k1 = 0, k2 = 0, k3 = 0;
        float e1 = 3.4e38f, e2 = 3.4e38f, e3 = 3.4e38f;       // row g+8
        int   j1 = 0, j2 = 0, j3 = 0;

        for (int nc = 0; nc < 4; ++nc) {
            const int cbase = h * 256 + nc * 64;
            float acc[8][4];
#pragma unroll
            for (int q = 0; q < 8; ++q)
#pragma unroll
                for (int r = 0; r < 4; ++r) acc[q][r] = 0.f;

            const uint32_t wbh = su + S_WHI + cbase * PB + boff;
#pragma unroll
            for (int p = 0; p < 4; ++p)
#pragma unroll
                for (int kk = 0; kk < 4; ++kk) {
                    uint32_t BH[4];
                    LDSM_X4(BH, wbh + p * 16 * PB + kk * 32);
                    MMA16816(acc[2 * p],     AH[kk], BH);
                    MMA16816(acc[2 * p + 1], AH[kk], BH + 2);
                    MMA16816(acc[2 * p],     AL[kk], BH);
                    MMA16816(acc[2 * p + 1], AL[kk], BH + 2);
                }

#pragma unroll
            for (int ha = 0; ha < 2; ++ha) {
#pragma unroll
                for (int ntl = 0; ntl < 4; ++ntl) {
                    const int nt = ha * 4 + ntl;
                    const int kloc = ntl * 8 + 2 * t4;
                    const int kg = cbase + ha * 32 + kloc;
                    const float2 eev = *(const float2*)(ee + kg);
                    const float D0 = xg0 + eev.x - 2.f * acc[nt][0];
                    const float D1 = xg0 + eev.y - 2.f * acc[nt][1];
                    const float D2 = xg8 + eev.x - 2.f * acc[nt][2];
                    const float D3 = xg8 + eev.y - 2.f * acc[nt][3];
                    top3_upd(D0, kg,     d1, k1, d2, k2, d3, k3);
                    top3_upd(D1, kg + 1, d1, k1, d2, k2, d3, k3);
                    top3_upd(D2, kg,     e1, j1, e2, j2, e3, j3);
                    top3_upd(D3, kg + 1, e1, j1, e2, j2, e3, j3);
                    *(float2*)(stg + g * 34 + kloc)       = make_float2(D0, D1);
                    *(float2*)(stg + (g + 8) * 34 + kloc) = make_float2(D2, D3);
                }
                __syncwarp();
                {
                    float* gpD = out + OFF_DIST + (size_t)(n0 + r0) * 512 + cbase + ha * 32;
#pragma unroll
                    for (int row = 0; row < 16; ++row)
                        gpD[(size_t)row * 512 + lane] = stg[row * 34 + lane];
                }
                __syncwarp();
            }
        }

        // ---- per-row top3 across the 4 lanes of each row ------------------
#pragma unroll
        for (int m = 1; m <= 2; m <<= 1) {
            float f1 = __shfl_xor_sync(0xffffffffu, d1, m);
            int   g1 = __shfl_xor_sync(0xffffffffu, k1, m);
            float f2 = __shfl_xor_sync(0xffffffffu, d2, m);
            int   g2 = __shfl_xor_sync(0xffffffffu, k2, m);
            float f3 = __shfl_xor_sync(0xffffffffu, d3, m);
            int   g3 = __shfl_xor_sync(0xffffffffu, k3, m);
            top3_ins(f1, g1, d1, k1, d2, k2, d3, k3);
            top3_ins(f2, g2, d1, k1, d2, k2, d3, k3);
            top3_ins(f3, g3, d1, k1, d2, k2, d3, k3);
            f1 = __shfl_xor_sync(0xffffffffu, e1, m);
            g1 = __shfl_xor_sync(0xffffffffu, j1, m);
            f2 = __shfl_xor_sync(0xffffffffu, e2, m);
            g2 = __shfl_xor_sync(0xffffffffu, j2, m);
            f3 = __shfl_xor_sync(0xffffffffu, e3, m);
            g3 = __shfl_xor_sync(0xffffffffu, j3, m);
            top3_ins(f1, g1, e1, j1, e2, j2, e3, j3);
            top3_ins(f2, g2, e1, j1, e2, j2, e3, j3);
            top3_ins(f3, g3, e1, j1, e2, j2, e3, j3);
        }
        if (t4 == 0) {
            const int rA = r0 + g, rB = rA + 8;
            ((float*)(sm + S_CD1))[h * 128 + rA] = d1;
            ((float*)(sm + S_CD2))[h * 128 + rA] = d2;
            ((float*)(sm + S_CD3))[h * 128 + rA] = d3;
            ((int*)  (sm + S_CK1))[h * 128 + rA] = k1;
            ((int*)  (sm + S_CK2))[h * 128 + rA] = k2;
            ((int*)  (sm + S_CK3))[h * 128 + rA] = k3;
            ((float*)(sm + S_CD1))[h * 128 + rB] = e1;
            ((float*)(sm + S_CD2))[h * 128 + rB] = e2;
            ((float*)(sm + S_CD3))[h * 128 + rB] = e3;
            ((int*)  (sm + S_CK1))[h * 128 + rB] = j1;
            ((int*)  (sm + S_CK2))[h * 128 + rB] = j2;
            ((int*)  (sm + S_CK3))[h * 128 + rB] = j3;
        }
        __syncthreads();

        // ---- one thread per row: merge halves, exact fp32 fixup -----------
        float rowmin = 0.f;
        if (t < 128) {
            const float* cd1 = (const float*)(sm + S_CD1);
            const float* cd2 = (const float*)(sm + S_CD2);
            const float* cd3 = (const float*)(sm + S_CD3);
            const int*   ck1 = (const int*)(sm + S_CK1);
            const int*   ck2 = (const int*)(sm + S_CK2);
            const int*   ck3 = (const int*)(sm + S_CK3);
            float m1 = cd1[t], m2 = cd2[t], m3 = cd3[t];
            int   q1 = ck1[t], q2 = ck2[t], q3 = ck3[t];
            top3_ins(cd1[128 + t], ck1[128 + t], m1, q1, m2, q2, m3, q3);
            top3_ins(cd2[128 + t], ck2[128 + t], m1, q1, m2, q2, m3, q3);
            top3_ins(cd3[128 + t], ck3[128 + t], m1, q1, m2, q2, m3, q3);
            const float xr2 = xxp[t] + xxp[128 + t] + xxp[256 + t] + xxp[384 + t];
            const float TAU = 2.5e-4f;
            if (m2 - m1 < TAU) {
                const float* xr = x + (size_t)bb * 65536 + hw0 + t;
                float bd = xr2 + ee[q1] - 2.f * dot_exact(xr, w + (size_t)q1 * 64);
                int   bk = q1;
                const float DB = xr2 + ee[q2] - 2.f * dot_exact(xr, w + (size_t)q2 * 64);
                if (lessk(DB, q2, bd, bk)) { bd = DB; bk = q2; }
                if (m3 - m1 < TAU) {
                    const float DC = xr2 + ee[q3] - 2.f * dot_exact(xr, w + (size_t)q3 * 64);
                    if (lessk(DC, q3, bd, bk)) { bd = DC; bk = q3; }
                }
                m1 = bd; q1 = bk;
            }
            ((int*)(sm + S_IDX))[t] = q1;
            out[OFF_EIDX + n0 + t] = (float)q1;
            rowmin = m1;
            atomicAdd(&g_cnt[q1], 1u);
        }

        // ---- loss partial: rows live in warps 0-3 -------------------------
#pragma unroll
        for (int off = 16; off > 0; off >>= 1)
            rowmin += __shfl_down_sync(0xffffffffu, rowmin, off);
        if (lane == 0 && wid < 4) ((float*)(sm + S_LRED))[wid] = rowmin;
        __syncthreads();
        if (t == 0) {
            const float* lr = (const float*)(sm + S_LRED);
            const float ctaLoss = lr[0] + lr[1] + lr[2] + lr[3];
            atomicAdd(&g_loss_i[bb],
                      (unsigned long long)((double)ctaLoss * 65536.0 + 0.5));
        }

        // ---- encodings: 16 warps x 8 rows, coalesced one-hot --------------
        {
            const int* idxs = (const int*)(sm + S_IDX);
#pragma unroll
            for (int rr = 0; rr < 8; ++rr) {
                const int row = wid * 8 + rr;
                const int ebk = idxs[row];
                float* ep = out + OFF_ENC + (size_t)(n0 + row) * 512;
#pragma unroll
                for (int i2 = 0; i2 < 16; ++i2) {
                    const int col = lane + 32 * i2;
                    ep[col] = (col == ebk) ? 1.f : 0.f;
                }
            }
        }

        // ---- q_out via SMEM transpose staging (reuses stage region) -------
        __syncthreads();
        {
            float* qs = (float*)(sm + S_STG);
            const int* idxs = (const int*)(sm + S_IDX);
            const int rr = wid * 8;
#pragma unroll
            for (int q = 0; q < 8; ++q) {
                const float* wr = w + (size_t)idxs[rr + q] * 64;
                qs[(rr + q) * 66 + lane]      = wr[lane];
                qs[(rr + q) * 66 + 32 + lane] = wr[32 + lane];
            }
            __syncthreads();
            float* qb = out + OFF_Q + (size_t)bb * 65536 + hw0;
#pragma unroll
            for (int i2 = 0; i2 < 16; ++i2) {
                const int u = t + 512 * i2;
                const int c = u >> 7, hl = u & 127;
                qb[(size_t)c * 1024 + hl] = qs[hl * 66 + c];
            }
        }

        tile = ntile;
        buf ^= 1;
    }

    // ---- last-CTA finalize: perplexity + loss, then reset scratch ---------
    __shared__ unsigned s_last;
    __threadfence();
    __syncthreads();
    if (t == 0) s_last = (atomicAdd(&g_tick, 1u) == gridDim.x - 1) ? 1u : 0u;
    __syncthreads();
    if (s_last) {
        __threadfence();
        const unsigned c0 = *(volatile unsigned*)&g_cnt[t];
        const float p0 = (float)c0 * (1.f / 65536.f);
        float s = p0 * logf(p0 + 1e-10f);
#pragma unroll
        for (int off = 16; off > 0; off >>= 1) s += __shfl_down_sync(0xffffffffu, s, off);
        float* red = (float*)(sm + S_LRED);
        if (lane == 0) red[wid] = s;
        __syncthreads();
        if (t == 0) {
            float tot = 0.f;
#pragma unroll
            for (int q = 0; q < 16; ++q) tot += red[q];
            out[OFF_PERP] = expf(-tot);
        }
        if (t < 64) {
            const unsigned long long v = *(volatile unsigned long long*)&g_loss_i[t];
            out[OFF_LOSS + t] = (float)((double)v * (1.25 / (65536.0 * 65536.0)));
            g_loss_i[t] = 0ull;
        }
        g_cnt[t] = 0u;
        if (t == 0) { g_tick = 0u; g_tile = 0u; }
    }
}

// ===========================================================================
extern "C" void kernel_launch(void* const* d_in, const int* in_sizes, int n_in,
                              void* d_out, int out_size) {
    const float* x = (const float*)d_in[0];
    const float* w = (const float*)d_in[1];
    float* out = (float*)d_out;

    cudaFuncSetAttribute(k_main, cudaFuncAttributeMaxDynamicSharedMemorySize, S_TOTAL);
    k_main<<<148, 512, S_TOTAL>>>(x, w, out);
}

// round 14
// speedup vs baseline: 1.1878x; 1.1878x over previous
#include <cuda_runtime.h>
#include <cuda_bf16.h>
#include <cstdint>

// ---------------- output layout (float32 concat, reference return order) ---
#define OFF_Q     0u
#define OFF_LOSS  4194304u
#define OFF_PERP  4194368u
#define OFF_ENC   4194369u
#define OFF_EIDX  37748801u
#define OFF_DIST  37814337u

// ---------------- dynamic SMEM layout (bytes) ------------------------------
#define PB 144                          // 72 bf16 pitch: ldmatrix conflict-free
#define S_WHI   0                       // 512 x 72 bf16 hi      73728
#define S_WLO   73728                   // 512 x 72 bf16 lo      73728
#define S_XHI   147456                  // 128 x 72 bf16 hi      18432
#define S_XLO   165888                  // 128 x 72 bf16 lo      18432
#define S_EE    184320                  // 512 f32                2048
#define S_XXP   186368                  // 4 x 128 f32            2048
#define S_IDX   188416                  // 128 int                 512
#define S_LRED  188928                  // 16 f32                   64
#define S_CD1   188992                  // [2][128] f32           1024
#define S_CD2   190016                  // [2][128] f32           1024
#define S_CK1   191040                  // [2][128] int           1024
#define S_CK2   192064                  // [2][128] int           1024
#define S_STG   193088                  // 16 warps x 16 x 34 f32 34816
#define S_TOTAL 227904                  // <= 232448
// q_out staging (128 x 66 f32 = 33792 B) reuses S_STG after dist writes.

// ---------------- scratch (allocation-free, self-resetting) ----------------
__device__ unsigned int        g_cnt[512];     // histogram
__device__ unsigned long long  g_loss_i[64];   // fixed-point loss partials
__device__ unsigned int        g_tick;         // CTA completion ticket

// ---------------- asm helpers ----------------------------------------------
__device__ __forceinline__ uint32_t smem_u32(const void* p) {
    uint32_t a;
    asm("{ .reg .u64 t; cvta.to.shared.u64 t, %1; cvt.u32.u64 %0, t; }" : "=r"(a) : "l"(p));
    return a;
}
#define LDSM_X4(r, a)                                                          \
    asm volatile("ldmatrix.sync.aligned.m8n8.x4.shared.b16 {%0,%1,%2,%3}, [%4];" \
        : "=r"((r)[0]), "=r"((r)[1]), "=r"((r)[2]), "=r"((r)[3]) : "r"(a))

#define MMA16816(d, a, b)                                                      \
    asm volatile("mma.sync.aligned.m16n8k16.row.col.f32.bf16.bf16.f32 "        \
        "{%0,%1,%2,%3}, {%4,%5,%6,%7}, {%8,%9}, {%0,%1,%2,%3};"                \
        : "+f"((d)[0]), "+f"((d)[1]), "+f"((d)[2]), "+f"((d)[3])               \
        : "r"((a)[0]), "r"((a)[1]), "r"((a)[2]), "r"((a)[3]),                  \
          "r"((b)[0]), "r"((b)[1]))

__device__ __forceinline__ unsigned short f2bf(float v) {
    __nv_bfloat16 b = __float2bfloat16_rn(v);
    return *reinterpret_cast<unsigned short*>(&b);
}
__device__ __forceinline__ float bf2f(unsigned short u) {
    __nv_bfloat16 b = *reinterpret_cast<__nv_bfloat16*>(&u);
    return __bfloat162float(b);
}
__device__ __forceinline__ uint32_t pack_hi(float a, float b) {
    return (uint32_t)f2bf(a) | ((uint32_t)f2bf(b) << 16);
}
__device__ __forceinline__ uint32_t pack_lo(float a, float b) {
    return (uint32_t)f2bf(a - bf2f(f2bf(a))) | ((uint32_t)f2bf(b - bf2f(f2bf(b))) << 16);
}

__device__ __forceinline__ void top2_upd(float d, int k, float& d1, int& k1,
                                         float& d2, int& k2) {
    if (d < d1)      { d2 = d1; k2 = k1; d1 = d; k1 = k; }
    else if (d < d2) { d2 = d; k2 = k; }
}
__device__ __forceinline__ void top2_merge(float e1, int j1, float e2, int j2,
                                           float& d1, int& k1, float& d2, int& k2) {
    if (e1 < d1 || (e1 == d1 && j1 < k1)) {
        if (d1 < e2 || (d1 == e2 && k1 < j2)) { d2 = d1; k2 = k1; }
        else                                  { d2 = e2; k2 = j2; }
        d1 = e1; k1 = j1;
    } else if (e1 < d2 || (e1 == d2 && j1 < k2)) {
        d2 = e1; k2 = j1;
    }
}
__device__ __forceinline__ float dot_exact(const float* xr, const float* wr) {
    float s = 0.f;
#pragma unroll
    for (int c = 0; c < 64; ++c) s = fmaf(xr[(size_t)c * 1024], wr[c], s);
    return s;
}

// ===========================================================================
// Persistent fused kernel: 152 CTAs x 512 thr (16 warps). Codebook converted
// ONCE per CTA; tiles (128 rows) strided statically. Per tile: warp pair owns
// 16 rows, each warp covers 256 codes. HMMA bf16 hi/lo 3-pass, full-domain
// top-2 + exact fp32 fixup (R10-proven numerics).
// ===========================================================================
__global__ void __launch_bounds__(512, 1)
k_main(const float* __restrict__ x, const float* __restrict__ w,
       float* __restrict__ out) {
    extern __shared__ char sm[];
    const uint32_t su = smem_u32(sm);
    const int t    = threadIdx.x;
    const int lane = t & 31;
    const int wid  = t >> 5;

    // ---- prolog (ONCE): w -> bf16 hi/lo pitched; ee[k] = ||w_k||^2 --------
    {
        const float4* w4 = (const float4*)w;
#pragma unroll
        for (int it = 0; it < 16; ++it) {
            const int u = t + 512 * it;
            const int k = u >> 4, j = u & 15;          // 16 threads per code
            float4 v = w4[(size_t)k * 16 + j];
            float s = v.x * v.x + v.y * v.y + v.z * v.z + v.w * v.w;
            s += __shfl_xor_sync(0xffffffffu, s, 8);
            s += __shfl_xor_sync(0xffffffffu, s, 4);
            s += __shfl_xor_sync(0xffffffffu, s, 2);
            s += __shfl_xor_sync(0xffffffffu, s, 1);
            if ((t & 15) == 0) ((float*)(sm + S_EE))[k] = s;
            *(uint2*)(sm + S_WHI + k * PB + j * 8) =
                make_uint2(pack_hi(v.x, v.y), pack_hi(v.z, v.w));
            *(uint2*)(sm + S_WLO + k * PB + j * 8) =
                make_uint2(pack_lo(v.x, v.y), pack_lo(v.z, v.w));
        }
    }

    // loop-invariant lane decompositions
    const int wg = wid >> 1, h = wid & 1;
    const int r0 = wg * 16;
    const int l7 = lane & 7, seg = lane >> 3, t4 = lane & 3, g = lane >> 2;
    const uint32_t aoff = (uint32_t)(r0 + l7 + ((seg & 1) << 3)) * PB + ((seg >> 1) << 4);
    const uint32_t boff = (uint32_t)(l7 + ((seg >> 1) << 3)) * PB + ((seg & 1) << 4);
    const float* ee  = (const float*)(sm + S_EE);
    const float* xxp = (const float*)(sm + S_XXP);
    float* stg = (float*)(sm + S_STG) + wid * (16 * 34);

    for (int tile = blockIdx.x; tile < 512; tile += gridDim.x) {
        const int n0  = tile << 7;
        const int bb  = tile >> 3;
        const int hw0 = (tile & 7) << 7;

        // ---- x tile: fp32 -> bf16 hi/lo (pitched); 4-way ||x||^2 ----------
        {
            const int hwl = t & 127, ch4 = t >> 7;     // ch4: 0..3
            const float* xg = x + (size_t)bb * 65536 + hw0 + hwl;
            float xxa = 0.f;
#pragma unroll
            for (int cc = 0; cc < 16; cc += 2) {
                const int c = ch4 * 16 + cc;
                float v0 = xg[(size_t)c * 1024];
                float v1 = xg[(size_t)(c + 1) * 1024];
                xxa = fmaf(v0, v0, fmaf(v1, v1, xxa));
                *(uint32_t*)(sm + S_XHI + hwl * PB + c * 2) = pack_hi(v0, v1);
                *(uint32_t*)(sm + S_XLO + hwl * PB + c * 2) = pack_lo(v0, v1);
            }
            ((float*)(sm + S_XXP))[ch4 * 128 + hwl] = xxa;
        }
        __syncthreads();

        // ---- A fragments (hi + lo) ----------------------------------------
        uint32_t AH[4][4], AL[4][4];
#pragma unroll
        for (int kk = 0; kk < 4; ++kk) {
            LDSM_X4(AH[kk], su + S_XHI + aoff + kk * 32);
            LDSM_X4(AL[kk], su + S_XLO + aoff + kk * 32);
        }
        const float xg0 = xxp[r0 + g]       + xxp[128 + r0 + g]
                        + xxp[256 + r0 + g] + xxp[384 + r0 + g];
        const float xg8 = xxp[r0 + g + 8]       + xxp[128 + r0 + g + 8]
                        + xxp[256 + r0 + g + 8] + xxp[384 + r0 + g + 8];

        float d1 = 3.4e38f, d2 = 3.4e38f;    // row g   top2 (full domain)
        int   k1 = 0, k2 = 0;
        float d1b = 3.4e38f, d2b = 3.4e38f;  // row g+8 top2
        int   k1b = 0, k2b = 0;

        for (int nc = 0; nc < 4; ++nc) {
            const int cbase = h * 256 + nc * 64;
            float acc[8][4];
#pragma unroll
            for (int q = 0; q < 8; ++q)
#pragma unroll
                for (int r = 0; r < 4; ++r) acc[q][r] = 0.f;

            const uint32_t wbh = su + S_WHI + cbase * PB + boff;
            const uint32_t wbl = su + S_WLO + cbase * PB + boff;
#pragma unroll
            for (int p = 0; p < 4; ++p)
#pragma unroll
                for (int kk = 0; kk < 4; ++kk) {
                    uint32_t BH[4], BL[4];
                    LDSM_X4(BH, wbh + p * 16 * PB + kk * 32);
                    LDSM_X4(BL, wbl + p * 16 * PB + kk * 32);
                    MMA16816(acc[2 * p],     AH[kk], BH);
                    MMA16816(acc[2 * p + 1], AH[kk], BH + 2);
                    MMA16816(acc[2 * p],     AH[kk], BL);
                    MMA16816(acc[2 * p + 1], AH[kk], BL + 2);
                    MMA16816(acc[2 * p],     AL[kk], BH);
                    MMA16816(acc[2 * p + 1], AL[kk], BH + 2);
                }

            // two 32-col halves: stage full-domain D -> top2 -> flush
#pragma unroll
            for (int ha = 0; ha < 2; ++ha) {
#pragma unroll
                for (int ntl = 0; ntl < 4; ++ntl) {
                    const int nt = ha * 4 + ntl;
                    const int kloc = ntl * 8 + 2 * t4;
                    const int kg = cbase + ha * 32 + kloc;
                    const float2 eev = *(const float2*)(ee + kg);
                    const float D0 = xg0 + eev.x - 2.f * acc[nt][0];
                    const float D1 = xg0 + eev.y - 2.f * acc[nt][1];
                    const float D2 = xg8 + eev.x - 2.f * acc[nt][2];
                    const float D3 = xg8 + eev.y - 2.f * acc[nt][3];
                    top2_upd(D0, kg,     d1, k1, d2, k2);
                    top2_upd(D1, kg + 1, d1, k1, d2, k2);
                    top2_upd(D2, kg,     d1b, k1b, d2b, k2b);
                    top2_upd(D3, kg + 1, d1b, k1b, d2b, k2b);
                    *(float2*)(stg + g * 34 + kloc)       = make_float2(D0, D1);
                    *(float2*)(stg + (g + 8) * 34 + kloc) = make_float2(D2, D3);
                }
                __syncwarp();
                {
                    float* gpD = out + OFF_DIST + (size_t)(n0 + r0) * 512 + cbase + ha * 32;
#pragma unroll
                    for (int row = 0; row < 16; ++row)
                        gpD[(size_t)row * 512 + lane] = stg[row * 34 + lane];
                }
                __syncwarp();
            }
        }

        // ---- per-row top2 across the 4 lanes of each row ------------------
#pragma unroll
        for (int m = 1; m <= 2; m <<= 1) {
            float e1 = __shfl_xor_sync(0xffffffffu, d1, m);
            int   j1 = __shfl_xor_sync(0xffffffffu, k1, m);
            float e2 = __shfl_xor_sync(0xffffffffu, d2, m);
            int   j2 = __shfl_xor_sync(0xffffffffu, k2, m);
            top2_merge(e1, j1, e2, j2, d1, k1, d2, k2);
            e1 = __shfl_xor_sync(0xffffffffu, d1b, m);
            j1 = __shfl_xor_sync(0xffffffffu, k1b, m);
            e2 = __shfl_xor_sync(0xffffffffu, d2b, m);
            j2 = __shfl_xor_sync(0xffffffffu, k2b, m);
            top2_merge(e1, j1, e2, j2, d1b, k1b, d2b, k2b);
        }
        if (t4 == 0) {
            const int rA = r0 + g, rB = rA + 8;
            ((float*)(sm + S_CD1))[h * 128 + rA] = d1;
            ((float*)(sm + S_CD2))[h * 128 + rA] = d2;
            ((int*)  (sm + S_CK1))[h * 128 + rA] = k1;
            ((int*)  (sm + S_CK2))[h * 128 + rA] = k2;
            ((float*)(sm + S_CD1))[h * 128 + rB] = d1b;
            ((float*)(sm + S_CD2))[h * 128 + rB] = d2b;
            ((int*)  (sm + S_CK1))[h * 128 + rB] = k1b;
            ((int*)  (sm + S_CK2))[h * 128 + rB] = k2b;
        }
        __syncthreads();

        // ---- one thread per row: merge halves, exact full-domain fixup ----
        float rowmin = 0.f;
        if (t < 128) {
            const float* cd1 = (const float*)(sm + S_CD1);
            const float* cd2 = (const float*)(sm + S_CD2);
            const int*   ck1 = (const int*)(sm + S_CK1);
            const int*   ck2 = (const int*)(sm + S_CK2);
            float m1 = cd1[t], m2 = cd2[t];
            int   q1 = ck1[t], q2 = ck2[t];
            top2_merge(cd1[128 + t], ck1[128 + t], cd2[128 + t], ck2[128 + t],
                       m1, q1, m2, q2);
            const float xr2 = xxp[t] + xxp[128 + t] + xxp[256 + t] + xxp[384 + t];
            const float TAU = 1e-5f;
            if (m2 - m1 < TAU) {   // exact fp32 recompute, full domain
                const float* xr = x + (size_t)bb * 65536 + hw0 + t;
                const float DA = xr2 + ee[q1] - 2.f * dot_exact(xr, w + (size_t)q1 * 64);
                const float DB = xr2 + ee[q2] - 2.f * dot_exact(xr, w + (size_t)q2 * 64);
                if (DB < DA || (DB == DA && q2 < q1)) { q1 = q2; m1 = DB; }
                else m1 = DA;
            }
            ((int*)(sm + S_IDX))[t] = q1;
            out[OFF_EIDX + n0 + t] = (float)q1;
            rowmin = m1;
            atomicAdd(&g_cnt[q1], 1u);
        }

        // ---- loss partial: rows live in warps 0-3 -------------------------
#pragma unroll
        for (int off = 16; off > 0; off >>= 1)
            rowmin += __shfl_down_sync(0xffffffffu, rowmin, off);
        if (lane == 0 && wid < 4) ((float*)(sm + S_LRED))[wid] = rowmin;
        __syncthreads();
        if (t == 0) {
            const float* lr = (const float*)(sm + S_LRED);
            const float ctaLoss = lr[0] + lr[1] + lr[2] + lr[3];
            atomicAdd(&g_loss_i[bb],
                      (unsigned long long)((double)ctaLoss * 65536.0 + 0.5));
        }

        // ---- encodings: 16 warps x 8 rows, coalesced one-hot --------------
        {
            const int* idxs = (const int*)(sm + S_IDX);
#pragma unroll
            for (int rr = 0; rr < 8; ++rr) {
                const int row = wid * 8 + rr;
                const int ebk = idxs[row];
                float* ep = out + OFF_ENC + (size_t)(n0 + row) * 512;
#pragma unroll
                for (int i2 = 0; i2 < 16; ++i2) {
                    const int col = lane + 32 * i2;
                    ep[col] = (col == ebk) ? 1.f : 0.f;
                }
            }
        }

        // ---- q_out via SMEM transpose staging (reuses stage region) -------
        __syncthreads();
        {
            float* qs = (float*)(sm + S_STG);
            const int* idxs = (const int*)(sm + S_IDX);
            const int rr = wid * 8;
#pragma unroll
            for (int q = 0; q < 8; ++q) {
                const float* wr = w + (size_t)idxs[rr + q] * 64;
                qs[(rr + q) * 66 + lane]      = wr[lane];
                qs[(rr + q) * 66 + 32 + lane] = wr[32 + lane];
            }
            __syncthreads();
            float* qb = out + OFF_Q + (size_t)bb * 65536 + hw0;
#pragma unroll
            for (int i2 = 0; i2 < 16; ++i2) {
                const int u = t + 512 * i2;
                const int c = u >> 7, hl = u & 127;
                qb[(size_t)c * 1024 + hl] = qs[hl * 66 + c];
            }
        }
    }

    // ---- last-CTA finalize: perplexity + loss, then reset scratch ---------
    __shared__ unsigned s_last;
    __threadfence();
    __syncthreads();
    if (t == 0) s_last = (atomicAdd(&g_tick, 1u) == gridDim.x - 1) ? 1u : 0u;
    __syncthreads();
    if (s_last) {
        __threadfence();
        const unsigned c0 = *(volatile unsigned*)&g_cnt[t];
        const float p0 = (float)c0 * (1.f / 65536.f);
        float s = p0 * logf(p0 + 1e-10f);
#pragma unroll
        for (int off = 16; off > 0; off >>= 1) s += __shfl_down_sync(0xffffffffu, s, off);
        float* red = (float*)(sm + S_LRED);
        if (lane == 0) red[wid] = s;
        __syncthreads();
        if (t == 0) {
            float tot = 0.f;
#pragma unroll
            for (int q = 0; q < 16; ++q) tot += red[q];
            out[OFF_PERP] = expf(-tot);
        }
        if (t < 64) {
            const unsigned long long v = *(volatile unsigned long long*)&g_loss_i[t];
            out[OFF_LOSS + t] = (float)((double)v * (1.25 / (65536.0 * 65536.0)));
            g_loss_i[t] = 0ull;
        }
        g_cnt[t] = 0u;
        if (t == 0) g_tick = 0u;
    }
}

// ===========================================================================
extern "C" void kernel_launch(void* const* d_in, const int* in_sizes, int n_in,
                              void* d_out, int out_size) {
    const float* x = (const float*)d_in[0];
    const float* w = (const float*)d_in[1];
    float* out = (float*)d_out;

    cudaFuncSetAttribute(k_main, cudaFuncAttributeMaxDynamicSharedMemorySize, S_TOTAL);
    k_main<<<152, 512, S_TOTAL>>>(x, w, out);
}

// round 15
// speedup vs baseline: 1.2316x; 1.0369x over previous
#include <cuda_runtime.h>
#include <cuda_bf16.h>
#include <cstdint>

// ---------------- output layout (float32 concat, reference return order) ---
#define OFF_Q     0u
#define OFF_LOSS  4194304u
#define OFF_PERP  4194368u
#define OFF_ENC   4194369u
#define OFF_EIDX  37748801u
#define OFF_DIST  37814337u

// ---------------- dynamic SMEM layout (bytes) ------------------------------
#define PB 144                          // 72 bf16 pitch: ldmatrix conflict-free
#define S_WHI   0                       // 512 x 72 bf16 hi      73728
#define S_WLO   73728                   // 512 x 72 bf16 lo      73728
#define S_XHI   147456                  // 128 x 72 bf16 hi      18432
#define S_XLO   165888                  // 128 x 72 bf16 lo      18432
#define S_EE    184320                  // 512 f32                2048
#define S_XXP   186368                  // 4 x 128 f32            2048
#define S_IDX   188416                  // 128 int                 512
#define S_LRED  188928                  // 16 f32                   64
#define S_CD1   188992                  // [2][128] f32           1024
#define S_CD2   190016                  // [2][128] f32           1024
#define S_CK1   191040                  // [2][128] int           1024
#define S_CK2   192064                  // [2][128] int           1024
#define S_STG   193088                  // 16 warps x 16 x 34 f32 34816
#define S_TOTAL 227904                  // <= 232448
// q_out staging (128 x 66 f32 = 33792 B) reuses S_STG after dist writes.

// ---------------- scratch (allocation-free, self-resetting) ----------------
__device__ unsigned int        g_cnt[512];     // histogram
__device__ unsigned long long  g_loss_i[64];   // fixed-point loss partials
__device__ unsigned int        g_tick;         // CTA completion ticket

// ---------------- asm helpers ----------------------------------------------
__device__ __forceinline__ uint32_t smem_u32(const void* p) {
    uint32_t a;
    asm("{ .reg .u64 t; cvta.to.shared.u64 t, %1; cvt.u32.u64 %0, t; }" : "=r"(a) : "l"(p));
    return a;
}
#define LDSM_X4(r, a)                                                          \
    asm volatile("ldmatrix.sync.aligned.m8n8.x4.shared.b16 {%0,%1,%2,%3}, [%4];" \
        : "=r"((r)[0]), "=r"((r)[1]), "=r"((r)[2]), "=r"((r)[3]) : "r"(a))

#define MMA16816(d, a, b)                                                      \
    asm volatile("mma.sync.aligned.m16n8k16.row.col.f32.bf16.bf16.f32 "        \
        "{%0,%1,%2,%3}, {%4,%5,%6,%7}, {%8,%9}, {%0,%1,%2,%3};"                \
        : "+f"((d)[0]), "+f"((d)[1]), "+f"((d)[2]), "+f"((d)[3])               \
        : "r"((a)[0]), "r"((a)[1]), "r"((a)[2]), "r"((a)[3]),                  \
          "r"((b)[0]), "r"((b)[1]))

__device__ __forceinline__ unsigned short f2bf(float v) {
    __nv_bfloat16 b = __float2bfloat16_rn(v);
    return *reinterpret_cast<unsigned short*>(&b);
}
__device__ __forceinline__ float bf2f(unsigned short u) {
    __nv_bfloat16 b = *reinterpret_cast<__nv_bfloat16*>(&u);
    return __bfloat162float(b);
}
__device__ __forceinline__ uint32_t pack_hi(float a, float b) {
    return (uint32_t)f2bf(a) | ((uint32_t)f2bf(b) << 16);
}
__device__ __forceinline__ uint32_t pack_lo(float a, float b) {
    return (uint32_t)f2bf(a - bf2f(f2bf(a))) | ((uint32_t)f2bf(b - bf2f(f2bf(b))) << 16);
}

__device__ __forceinline__ void top2_upd(float d, int k, float& d1, int& k1,
                                         float& d2, int& k2) {
    if (d < d1)      { d2 = d1; k2 = k1; d1 = d; k1 = k; }
    else if (d < d2) { d2 = d; k2 = k; }
}
__device__ __forceinline__ void top2_merge(float e1, int j1, float e2, int j2,
                                           float& d1, int& k1, float& d2, int& k2) {
    if (e1 < d1 || (e1 == d1 && j1 < k1)) {
        if (d1 < e2 || (d1 == e2 && k1 < j2)) { d2 = d1; k2 = k1; }
        else                                  { d2 = e2; k2 = j2; }
        d1 = e1; k1 = j1;
    } else if (e1 < d2 || (e1 == d2 && j1 < k2)) {
        d2 = e1; k2 = j1;
    }
}
__device__ __forceinline__ float dot_exact(const float* xr, const float* wr) {
    float s = 0.f;
#pragma unroll
    for (int c = 0; c < 64; ++c) s = fmaf(xr[(size_t)c * 1024], wr[c], s);
    return s;
}

// ===========================================================================
// Persistent fused kernel: 152 CTAs x 512 thr (16 warps). Codebook converted
// ONCE per CTA; tiles (128 rows) strided statically. Per tile: warp pair owns
// 16 rows, each warp covers 256 codes. HMMA bf16 hi/lo 3-pass with ILP-
// reordered issue (8 independent accumulator chains). Full-domain top-2 +
// exact fp32 fixup (R10-proven numerics; accumulation order preserved).
// ===========================================================================
__global__ void __launch_bounds__(512, 1)
k_main(const float* __restrict__ x, const float* __restrict__ w,
       float* __restrict__ out) {
    extern __shared__ char sm[];
    const uint32_t su = smem_u32(sm);
    const int t    = threadIdx.x;
    const int lane = t & 31;
    const int wid  = t >> 5;

    // ---- prolog (ONCE): w -> bf16 hi/lo pitched; ee[k] = ||w_k||^2 --------
    {
        const float4* w4 = (const float4*)w;
#pragma unroll
        for (int it = 0; it < 16; ++it) {
            const int u = t + 512 * it;
            const int k = u >> 4, j = u & 15;          // 16 threads per code
            float4 v = w4[(size_t)k * 16 + j];
            float s = v.x * v.x + v.y * v.y + v.z * v.z + v.w * v.w;
            s += __shfl_xor_sync(0xffffffffu, s, 8);
            s += __shfl_xor_sync(0xffffffffu, s, 4);
            s += __shfl_xor_sync(0xffffffffu, s, 2);
            s += __shfl_xor_sync(0xffffffffu, s, 1);
            if ((t & 15) == 0) ((float*)(sm + S_EE))[k] = s;
            *(uint2*)(sm + S_WHI + k * PB + j * 8) =
                make_uint2(pack_hi(v.x, v.y), pack_hi(v.z, v.w));
            *(uint2*)(sm + S_WLO + k * PB + j * 8) =
                make_uint2(pack_lo(v.x, v.y), pack_lo(v.z, v.w));
        }
    }

    // loop-invariant lane decompositions
    const int wg = wid >> 1, h = wid & 1;
    const int r0 = wg * 16;
    const int l7 = lane & 7, seg = lane >> 3, t4 = lane & 3, g = lane >> 2;
    const uint32_t aoff = (uint32_t)(r0 + l7 + ((seg & 1) << 3)) * PB + ((seg >> 1) << 4);
    const uint32_t boff = (uint32_t)(l7 + ((seg >> 1) << 3)) * PB + ((seg & 1) << 4);
    const float* ee  = (const float*)(sm + S_EE);
    const float* xxp = (const float*)(sm + S_XXP);
    float* stg = (float*)(sm + S_STG) + wid * (16 * 34);

    for (int tile = blockIdx.x; tile < 512; tile += gridDim.x) {
        const int n0  = tile << 7;
        const int bb  = tile >> 3;
        const int hw0 = (tile & 7) << 7;

        // ---- x tile: fp32 -> bf16 hi/lo (pitched); 4-way ||x||^2 ----------
        {
            const int hwl = t & 127, ch4 = t >> 7;     // ch4: 0..3
            const float* xg = x + (size_t)bb * 65536 + hw0 + hwl;
            float xxa = 0.f;
#pragma unroll
            for (int cc = 0; cc < 16; cc += 2) {
                const int c = ch4 * 16 + cc;
                float v0 = xg[(size_t)c * 1024];
                float v1 = xg[(size_t)(c + 1) * 1024];
                xxa = fmaf(v0, v0, fmaf(v1, v1, xxa));
                *(uint32_t*)(sm + S_XHI + hwl * PB + c * 2) = pack_hi(v0, v1);
                *(uint32_t*)(sm + S_XLO + hwl * PB + c * 2) = pack_lo(v0, v1);
            }
            ((float*)(sm + S_XXP))[ch4 * 128 + hwl] = xxa;
        }
        __syncthreads();

        // ---- A fragments (hi + lo) ----------------------------------------
        uint32_t AH[4][4], AL[4][4];
#pragma unroll
        for (int kk = 0; kk < 4; ++kk) {
            LDSM_X4(AH[kk], su + S_XHI + aoff + kk * 32);
            LDSM_X4(AL[kk], su + S_XLO + aoff + kk * 32);
        }
        const float xg0 = xxp[r0 + g]       + xxp[128 + r0 + g]
                        + xxp[256 + r0 + g] + xxp[384 + r0 + g];
        const float xg8 = xxp[r0 + g + 8]       + xxp[128 + r0 + g + 8]
                        + xxp[256 + r0 + g + 8] + xxp[384 + r0 + g + 8];

        float d1 = 3.4e38f, d2 = 3.4e38f;    // row g   top2 (full domain)
        int   k1 = 0, k2 = 0;
        float d1b = 3.4e38f, d2b = 3.4e38f;  // row g+8 top2
        int   k1b = 0, k2b = 0;

        for (int nc = 0; nc < 4; ++nc) {
            const int cbase = h * 256 + nc * 64;
            float acc[8][4];
#pragma unroll
            for (int q = 0; q < 8; ++q)
#pragma unroll
                for (int r = 0; r < 4; ++r) acc[q][r] = 0.f;

            const uint32_t wbh = su + S_WHI + cbase * PB + boff;
            const uint32_t wbl = su + S_WLO + cbase * PB + boff;
            // kk-outer, pass-major over p: 8 independent accumulator chains
            // between dependent HMMAs. Per-accumulator contribution order is
            // unchanged (HH, HL, LH per kk) -> bit-identical to R10/R14.
#pragma unroll
            for (int kk = 0; kk < 4; ++kk) {
                uint32_t BH[4][4], BL[4][4];
#pragma unroll
                for (int p = 0; p < 4; ++p) {
                    LDSM_X4(BH[p], wbh + p * 16 * PB + kk * 32);
                    LDSM_X4(BL[p], wbl + p * 16 * PB + kk * 32);
                }
#pragma unroll
                for (int p = 0; p < 4; ++p) {
                    MMA16816(acc[2 * p],     AH[kk], BH[p]);
                    MMA16816(acc[2 * p + 1], AH[kk], BH[p] + 2);
                }
#pragma unroll
                for (int p = 0; p < 4; ++p) {
                    MMA16816(acc[2 * p],     AH[kk], BL[p]);
                    MMA16816(acc[2 * p + 1], AH[kk], BL[p] + 2);
                }
#pragma unroll
                for (int p = 0; p < 4; ++p) {
                    MMA16816(acc[2 * p],     AL[kk], BH[p]);
                    MMA16816(acc[2 * p + 1], AL[kk], BH[p] + 2);
                }
            }

            // two 32-col halves: stage full-domain D -> top2 -> flush
#pragma unroll
            for (int ha = 0; ha < 2; ++ha) {
#pragma unroll
                for (int ntl = 0; ntl < 4; ++ntl) {
                    const int nt = ha * 4 + ntl;
                    const int kloc = ntl * 8 + 2 * t4;
                    const int kg = cbase + ha * 32 + kloc;
                    const float2 eev = *(const float2*)(ee + kg);
                    const float D0 = xg0 + eev.x - 2.f * acc[nt][0];
                    const float D1 = xg0 + eev.y - 2.f * acc[nt][1];
                    const float D2 = xg8 + eev.x - 2.f * acc[nt][2];
                    const float D3 = xg8 + eev.y - 2.f * acc[nt][3];
                    top2_upd(D0, kg,     d1, k1, d2, k2);
                    top2_upd(D1, kg + 1, d1, k1, d2, k2);
                    top2_upd(D2, kg,     d1b, k1b, d2b, k2b);
                    top2_upd(D3, kg + 1, d1b, k1b, d2b, k2b);
                    *(float2*)(stg + g * 34 + kloc)       = make_float2(D0, D1);
                    *(float2*)(stg + (g + 8) * 34 + kloc) = make_float2(D2, D3);
                }
                __syncwarp();
                {
                    float* gpD = out + OFF_DIST + (size_t)(n0 + r0) * 512 + cbase + ha * 32;
#pragma unroll
                    for (int row = 0; row < 16; ++row)
                        gpD[(size_t)row * 512 + lane] = stg[row * 34 + lane];
                }
                __syncwarp();
            }
        }

        // ---- per-row top2 across the 4 lanes of each row ------------------
#pragma unroll
        for (int m = 1; m <= 2; m <<= 1) {
            float e1 = __shfl_xor_sync(0xffffffffu, d1, m);
            int   j1 = __shfl_xor_sync(0xffffffffu, k1, m);
            float e2 = __shfl_xor_sync(0xffffffffu, d2, m);
            int   j2 = __shfl_xor_sync(0xffffffffu, k2, m);
            top2_merge(e1, j1, e2, j2, d1, k1, d2, k2);
            e1 = __shfl_xor_sync(0xffffffffu, d1b, m);
            j1 = __shfl_xor_sync(0xffffffffu, k1b, m);
            e2 = __shfl_xor_sync(0xffffffffu, d2b, m);
            j2 = __shfl_xor_sync(0xffffffffu, k2b, m);
            top2_merge(e1, j1, e2, j2, d1b, k1b, d2b, k2b);
        }
        if (t4 == 0) {
            const int rA = r0 + g, rB = rA + 8;
            ((float*)(sm + S_CD1))[h * 128 + rA] = d1;
            ((float*)(sm + S_CD2))[h * 128 + rA] = d2;
            ((int*)  (sm + S_CK1))[h * 128 + rA] = k1;
            ((int*)  (sm + S_CK2))[h * 128 + rA] = k2;
            ((float*)(sm + S_CD1))[h * 128 + rB] = d1b;
            ((float*)(sm + S_CD2))[h * 128 + rB] = d2b;
            ((int*)  (sm + S_CK1))[h * 128 + rB] = k1b;
            ((int*)  (sm + S_CK2))[h * 128 + rB] = k2b;
        }
        __syncthreads();

        // ---- one thread per row: merge halves, exact full-domain fixup ----
        float rowmin = 0.f;
        if (t < 128) {
            const float* cd1 = (const float*)(sm + S_CD1);
            const float* cd2 = (const float*)(sm + S_CD2);
            const int*   ck1 = (const int*)(sm + S_CK1);
            const int*   ck2 = (const int*)(sm + S_CK2);
            float m1 = cd1[t], m2 = cd2[t];
            int   q1 = ck1[t], q2 = ck2[t];
            top2_merge(cd1[128 + t], ck1[128 + t], cd2[128 + t], ck2[128 + t],
                       m1, q1, m2, q2);
            const float xr2 = xxp[t] + xxp[128 + t] + xxp[256 + t] + xxp[384 + t];
            const float TAU = 1e-5f;
            if (m2 - m1 < TAU) {   // exact fp32 recompute, full domain
                const float* xr = x + (size_t)bb * 65536 + hw0 + t;
                const float DA = xr2 + ee[q1] - 2.f * dot_exact(xr, w + (size_t)q1 * 64);
                const float DB = xr2 + ee[q2] - 2.f * dot_exact(xr, w + (size_t)q2 * 64);
                if (DB < DA || (DB == DA && q2 < q1)) { q1 = q2; m1 = DB; }
                else m1 = DA;
            }
            ((int*)(sm + S_IDX))[t] = q1;
            out[OFF_EIDX + n0 + t] = (float)q1;
            rowmin = m1;
            atomicAdd(&g_cnt[q1], 1u);
        }

        // ---- loss partial: rows live in warps 0-3 -------------------------
#pragma unroll
        for (int off = 16; off > 0; off >>= 1)
            rowmin += __shfl_down_sync(0xffffffffu, rowmin, off);
        if (lane == 0 && wid < 4) ((float*)(sm + S_LRED))[wid] = rowmin;
        __syncthreads();
        if (t == 0) {
            const float* lr = (const float*)(sm + S_LRED);
            const float ctaLoss = lr[0] + lr[1] + lr[2] + lr[3];
            atomicAdd(&g_loss_i[bb],
                      (unsigned long long)((double)ctaLoss * 65536.0 + 0.5));
        }

        // ---- encodings: one-hot rows via aligned STG.128 ------------------
        // row base = OFF_ENC + n*512 == 1 (mod 4) -> [3..511) is 16B-aligned:
        // 127 float4 quads + 3 head scalars + 1 tail scalar per row.
        {
            const int* idxs = (const int*)(sm + S_IDX);
#pragma unroll
            for (int rr = 0; rr < 8; ++rr) {
                const int row = wid * 8 + rr;
                const int ebk = idxs[row];
                float* ep = out + OFF_ENC + (size_t)(n0 + row) * 512;
                if (lane < 3)       ep[lane] = (lane == ebk) ? 1.f : 0.f;
                else if (lane == 3) ep[511]  = (511 == ebk) ? 1.f : 0.f;
                const int qhot = (ebk - 3) >> 2;   // quad containing ebk (ebk>=3)
#pragma unroll
                for (int s2 = 0; s2 < 4; ++s2) {
                    const int q = lane + 32 * s2;
                    if (q < 127) {
                        float4 v = make_float4(0.f, 0.f, 0.f, 0.f);
                        if (q == qhot) {
                            const int b = 3 + 4 * q;
                            v.x = (b == ebk);     v.y = (b + 1 == ebk);
                            v.z = (b + 2 == ebk); v.w = (b + 3 == ebk);
                        }
                        *(float4*)(ep + 3 + 4 * q) = v;
                    }
                }
            }
        }

        // ---- q_out via SMEM transpose staging (reuses stage region) -------
        __syncthreads();
        {
            float* qs = (float*)(sm + S_STG);
            const int* idxs = (const int*)(sm + S_IDX);
            const int rr = wid * 8;
#pragma unroll
            for (int q = 0; q < 8; ++q) {
                const float* wr = w + (size_t)idxs[rr + q] * 64;
                qs[(rr + q) * 66 + lane]      = wr[lane];
                qs[(rr + q) * 66 + 32 + lane] = wr[32 + lane];
            }
            __syncthreads();
            float* qb = out + OFF_Q + (size_t)bb * 65536 + hw0;
#pragma unroll
            for (int i2 = 0; i2 < 16; ++i2) {
                const int u = t + 512 * i2;
                const int c = u >> 7, hl = u & 127;
                qb[(size_t)c * 1024 + hl] = qs[hl * 66 + c];
            }
        }
    }

    // ---- last-CTA finalize: perplexity + loss, then reset scratch ---------
    __shared__ unsigned s_last;
    __threadfence();
    __syncthreads();
    if (t == 0) s_last = (atomicAdd(&g_tick, 1u) == gridDim.x - 1) ? 1u : 0u;
    __syncthreads();
    if (s_last) {
        __threadfence();
        const unsigned c0 = *(volatile unsigned*)&g_cnt[t];
        const float p0 = (float)c0 * (1.f / 65536.f);
        float s = p0 * logf(p0 + 1e-10f);
#pragma unroll
        for (int off = 16; off > 0; off >>= 1) s += __shfl_down_sync(0xffffffffu, s, off);
        float* red = (float*)(sm + S_LRED);
        if (lane == 0) red[wid] = s;
        __syncthreads();
        if (t == 0) {
            float tot = 0.f;
#pragma unroll
            for (int q = 0; q < 16; ++q) tot += red[q];
            out[OFF_PERP] = expf(-tot);
        }
        if (t < 64) {
            const unsigned long long v = *(volatile unsigned long long*)&g_loss_i[t];
            out[OFF_LOSS + t] = (float)((double)v * (1.25 / (65536.0 * 65536.0)));
            g_loss_i[t] = 0ull;
        }
        g_cnt[t] = 0u;
        if (t == 0) g_tick = 0u;
    }
}

// ===========================================================================
extern "C" void kernel_launch(void* const* d_in, const int* in_sizes, int n_in,
                              void* d_out, int out_size) {
    const float* x = (const float*)d_in[0];
    const float* w = (const float*)d_in[1];
    float* out = (float*)d_out;

    cudaFuncSetAttribute(k_main, cudaFuncAttributeMaxDynamicSharedMemorySize, S_TOTAL);
    k_main<<<152, 512, S_TOTAL>>>(x, w, out);
}

// round 16
// speedup vs baseline: 1.2348x; 1.0026x over previous
#include <cuda_runtime.h>
#include <cuda_bf16.h>
#include <cstdint>

// ---------------- output layout (float32 concat, reference return order) ---
#define OFF_Q     0u
#define OFF_LOSS  4194304u
#define OFF_PERP  4194368u
#define OFF_ENC   4194369u
#define OFF_EIDX  37748801u
#define OFF_DIST  37814337u

// ---------------- dynamic SMEM layout (bytes) ------------------------------
#define PB 144                          // 72 bf16 pitch: ldmatrix conflict-free
#define S_WHI   0                       // 512 x 72 bf16 hi      73728
#define S_WLO   73728                   // 512 x 72 bf16 lo      73728
#define S_XHI   147456                  // 64 x 72 bf16 hi        9216
#define S_XLO   156672                  // 64 x 72 bf16 lo        9216
#define S_EE    165888                  // 512 f32                2048
#define S_XXP   167936                  // 4 x 64 f32             1024
#define S_IDX   168960                  // 64 int                  256
#define S_LRED  169216                  // 16 f32                   64
#define S_CD1   169280                  // [4][64] f32            1024
#define S_CD2   170304                  // [4][64] f32            1024
#define S_CK1   171328                  // [4][64] int            1024
#define S_CK2   172352                  // [4][64] int            1024
#define S_STG   173376                  // 16 warps x 16 x 34 f32 34816
#define S_TOTAL 208192                  // <= 232448
// q_out staging (64 x 66 f32 = 16896 B) reuses S_STG after dist writes.

// ---------------- scratch (allocation-free, self-resetting) ----------------
__device__ unsigned int        g_cnt[512];     // histogram
__device__ unsigned long long  g_loss_i[64];   // fixed-point loss partials
__device__ unsigned int        g_tick;         // CTA completion ticket

// ---------------- asm helpers ----------------------------------------------
__device__ __forceinline__ uint32_t smem_u32(const void* p) {
    uint32_t a;
    asm("{ .reg .u64 t; cvta.to.shared.u64 t, %1; cvt.u32.u64 %0, t; }" : "=r"(a) : "l"(p));
    return a;
}
#define LDSM_X4(r, a)                                                          \
    asm volatile("ldmatrix.sync.aligned.m8n8.x4.shared.b16 {%0,%1,%2,%3}, [%4];" \
        : "=r"((r)[0]), "=r"((r)[1]), "=r"((r)[2]), "=r"((r)[3]) : "r"(a))

#define MMA16816(d, a, b)                                                      \
    asm volatile("mma.sync.aligned.m16n8k16.row.col.f32.bf16.bf16.f32 "        \
        "{%0,%1,%2,%3}, {%4,%5,%6,%7}, {%8,%9}, {%0,%1,%2,%3};"                \
        : "+f"((d)[0]), "+f"((d)[1]), "+f"((d)[2]), "+f"((d)[3])               \
        : "r"((a)[0]), "r"((a)[1]), "r"((a)[2]), "r"((a)[3]),                  \
          "r"((b)[0]), "r"((b)[1]))

__device__ __forceinline__ unsigned short f2bf(float v) {
    __nv_bfloat16 b = __float2bfloat16_rn(v);
    return *reinterpret_cast<unsigned short*>(&b);
}
__device__ __forceinline__ float bf2f(unsigned short u) {
    __nv_bfloat16 b = *reinterpret_cast<__nv_bfloat16*>(&u);
    return __bfloat162float(b);
}
__device__ __forceinline__ uint32_t pack_hi(float a, float b) {
    return (uint32_t)f2bf(a) | ((uint32_t)f2bf(b) << 16);
}
__device__ __forceinline__ uint32_t pack_lo(float a, float b) {
    return (uint32_t)f2bf(a - bf2f(f2bf(a))) | ((uint32_t)f2bf(b - bf2f(f2bf(b))) << 16);
}

__device__ __forceinline__ void top2_upd(float d, int k, float& d1, int& k1,
                                         float& d2, int& k2) {
    if (d < d1)      { d2 = d1; k2 = k1; d1 = d; k1 = k; }
    else if (d < d2) { d2 = d; k2 = k; }
}
__device__ __forceinline__ void top2_merge(float e1, int j1, float e2, int j2,
                                           float& d1, int& k1, float& d2, int& k2) {
    if (e1 < d1 || (e1 == d1 && j1 < k1)) {
        if (d1 < e2 || (d1 == e2 && k1 < j2)) { d2 = d1; k2 = k1; }
        else                                  { d2 = e2; k2 = j2; }
        d1 = e1; k1 = j1;
    } else if (e1 < d2 || (e1 == d2 && j1 < k2)) {
        d2 = e1; k2 = j1;
    }
}
__device__ __forceinline__ float dot_exact(const float* xr, const float* wr) {
    float s = 0.f;
#pragma unroll
    for (int c = 0; c < 64; ++c) s = fmaf(xr[(size_t)c * 1024], wr[c], s);
    return s;
}

// ===========================================================================
// Persistent fused kernel: 152 CTAs x 512 thr (16 warps). Codebook converted
// ONCE per CTA. 1024 tiles of 64 rows (load-balanced: 96% last-wave util).
// Per tile: 4 warps per 16-row group, each warp owns a 128-col quarter.
// HMMA bf16 hi/lo 3-pass, ILP-reordered; full-domain top-2 + exact fixup.
// ===========================================================================
__global__ void __launch_bounds__(512, 1)
k_main(const float* __restrict__ x, const float* __restrict__ w,
       float* __restrict__ out) {
    extern __shared__ char sm[];
    const uint32_t su = smem_u32(sm);
    const int t    = threadIdx.x;
    const int lane = t & 31;
    const int wid  = t >> 5;

    // ---- prolog (ONCE): w -> bf16 hi/lo pitched; ee[k] = ||w_k||^2 --------
    {
        const float4* w4 = (const float4*)w;
#pragma unroll
        for (int it = 0; it < 16; ++it) {
            const int u = t + 512 * it;
            const int k = u >> 4, j = u & 15;          // 16 threads per code
            float4 v = w4[(size_t)k * 16 + j];
            float s = v.x * v.x + v.y * v.y + v.z * v.z + v.w * v.w;
            s += __shfl_xor_sync(0xffffffffu, s, 8);
            s += __shfl_xor_sync(0xffffffffu, s, 4);
            s += __shfl_xor_sync(0xffffffffu, s, 2);
            s += __shfl_xor_sync(0xffffffffu, s, 1);
            if ((t & 15) == 0) ((float*)(sm + S_EE))[k] = s;
            *(uint2*)(sm + S_WHI + k * PB + j * 8) =
                make_uint2(pack_hi(v.x, v.y), pack_hi(v.z, v.w));
            *(uint2*)(sm + S_WLO + k * PB + j * 8) =
                make_uint2(pack_lo(v.x, v.y), pack_lo(v.z, v.w));
        }
    }

    // loop-invariant lane decompositions
    const int wq = wid >> 2;              // row group (0..3): 16 rows
    const int hq = wid & 3;               // col quarter (0..3): 128 cols
    const int r0 = wq * 16;
    const int l7 = lane & 7, seg = lane >> 3, t4 = lane & 3, g = lane >> 2;
    const uint32_t aoff = (uint32_t)(r0 + l7 + ((seg & 1) << 3)) * PB + ((seg >> 1) << 4);
    const uint32_t boff = (uint32_t)(l7 + ((seg >> 1) << 3)) * PB + ((seg & 1) << 4);
    const float* ee  = (const float*)(sm + S_EE);
    const float* xxp = (const float*)(sm + S_XXP);
    float* stg = (float*)(sm + S_STG) + wid * (16 * 34);

    for (int tile = blockIdx.x; tile < 1024; tile += gridDim.x) {
        const int n0  = tile << 6;            // 64 rows / tile
        const int bb  = tile >> 4;
        const int hw0 = (tile & 15) << 6;

        // ---- x tile: fp32 -> bf16 hi/lo (threads 0-255); 4-way ||x||^2 ----
        if (t < 256) {
            const int hwl = t & 63, ch4 = t >> 6;      // ch4: 0..3 (16 ch each)
            const float* xg = x + (size_t)bb * 65536 + hw0 + hwl;
            float xxa = 0.f;
#pragma unroll
            for (int cc = 0; cc < 16; cc += 2) {
                const int c = ch4 * 16 + cc;
                float v0 = xg[(size_t)c * 1024];
                float v1 = xg[(size_t)(c + 1) * 1024];
                xxa = fmaf(v0, v0, fmaf(v1, v1, xxa));
                *(uint32_t*)(sm + S_XHI + hwl * PB + c * 2) = pack_hi(v0, v1);
                *(uint32_t*)(sm + S_XLO + hwl * PB + c * 2) = pack_lo(v0, v1);
            }
            ((float*)(sm + S_XXP))[ch4 * 64 + hwl] = xxa;
        }
        __syncthreads();

        // ---- A fragments (hi + lo) ----------------------------------------
        uint32_t AH[4][4], AL[4][4];
#pragma unroll
        for (int kk = 0; kk < 4; ++kk) {
            LDSM_X4(AH[kk], su + S_XHI + aoff + kk * 32);
            LDSM_X4(AL[kk], su + S_XLO + aoff + kk * 32);
        }
        const float xg0 = xxp[r0 + g]      + xxp[64 + r0 + g]
                        + xxp[128 + r0 + g] + xxp[192 + r0 + g];
        const float xg8 = xxp[r0 + g + 8]      + xxp[64 + r0 + g + 8]
                        + xxp[128 + r0 + g + 8] + xxp[192 + r0 + g + 8];

        float d1 = 3.4e38f, d2 = 3.4e38f;    // row g   top2 (full domain)
        int   k1 = 0, k2 = 0;
        float d1b = 3.4e38f, d2b = 3.4e38f;  // row g+8 top2
        int   k1b = 0, k2b = 0;

        for (int nc = 0; nc < 2; ++nc) {
            const int cbase = hq * 128 + nc * 64;
            float acc[8][4];
#pragma unroll
            for (int q = 0; q < 8; ++q)
#pragma unroll
                for (int r = 0; r < 4; ++r) acc[q][r] = 0.f;

            const uint32_t wbh = su + S_WHI + cbase * PB + boff;
            const uint32_t wbl = su + S_WLO + cbase * PB + boff;
            // kk-outer, pass-major: 8 independent accumulator chains; per-
            // accumulator order (HH, HL, LH per kk) identical to R15.
#pragma unroll
            for (int kk = 0; kk < 4; ++kk) {
                uint32_t BH[4][4], BL[4][4];
#pragma unroll
                for (int p = 0; p < 4; ++p) {
                    LDSM_X4(BH[p], wbh + p * 16 * PB + kk * 32);
                    LDSM_X4(BL[p], wbl + p * 16 * PB + kk * 32);
                }
#pragma unroll
                for (int p = 0; p < 4; ++p) {
                    MMA16816(acc[2 * p],     AH[kk], BH[p]);
                    MMA16816(acc[2 * p + 1], AH[kk], BH[p] + 2);
                }
#pragma unroll
                for (int p = 0; p < 4; ++p) {
                    MMA16816(acc[2 * p],     AH[kk], BL[p]);
                    MMA16816(acc[2 * p + 1], AH[kk], BL[p] + 2);
                }
#pragma unroll
                for (int p = 0; p < 4; ++p) {
                    MMA16816(acc[2 * p],     AL[kk], BH[p]);
                    MMA16816(acc[2 * p + 1], AL[kk], BH[p] + 2);
                }
            }

            // two 32-col halves: stage full-domain D -> top2 -> flush
#pragma unroll
            for (int ha = 0; ha < 2; ++ha) {
#pragma unroll
                for (int ntl = 0; ntl < 4; ++ntl) {
                    const int nt = ha * 4 + ntl;
                    const int kloc = ntl * 8 + 2 * t4;
                    const int kg = cbase + ha * 32 + kloc;
                    const float2 eev = *(const float2*)(ee + kg);
                    const float D0 = xg0 + eev.x - 2.f * acc[nt][0];
                    const float D1 = xg0 + eev.y - 2.f * acc[nt][1];
                    const float D2 = xg8 + eev.x - 2.f * acc[nt][2];
                    const float D3 = xg8 + eev.y - 2.f * acc[nt][3];
                    top2_upd(D0, kg,     d1, k1, d2, k2);
                    top2_upd(D1, kg + 1, d1, k1, d2, k2);
                    top2_upd(D2, kg,     d1b, k1b, d2b, k2b);
                    top2_upd(D3, kg + 1, d1b, k1b, d2b, k2b);
                    *(float2*)(stg + g * 34 + kloc)       = make_float2(D0, D1);
                    *(float2*)(stg + (g + 8) * 34 + kloc) = make_float2(D2, D3);
                }
                __syncwarp();
                {
                    float* gpD = out + OFF_DIST + (size_t)(n0 + r0) * 512 + cbase + ha * 32;
#pragma unroll
                    for (int row = 0; row < 16; ++row)
                        gpD[(size_t)row * 512 + lane] = stg[row * 34 + lane];
                }
                __syncwarp();
            }
        }

        // ---- per-row top2 across the 4 lanes of each row ------------------
#pragma unroll
        for (int m = 1; m <= 2; m <<= 1) {
            float e1 = __shfl_xor_sync(0xffffffffu, d1, m);
            int   j1 = __shfl_xor_sync(0xffffffffu, k1, m);
            float e2 = __shfl_xor_sync(0xffffffffu, d2, m);
            int   j2 = __shfl_xor_sync(0xffffffffu, k2, m);
            top2_merge(e1, j1, e2, j2, d1, k1, d2, k2);
            e1 = __shfl_xor_sync(0xffffffffu, d1b, m);
            j1 = __shfl_xor_sync(0xffffffffu, k1b, m);
            e2 = __shfl_xor_sync(0xffffffffu, d2b, m);
            j2 = __shfl_xor_sync(0xffffffffu, k2b, m);
            top2_merge(e1, j1, e2, j2, d1b, k1b, d2b, k2b);
        }
        if (t4 == 0) {
            const int rA = r0 + g, rB = rA + 8;
            ((float*)(sm + S_CD1))[hq * 64 + rA] = d1;
            ((float*)(sm + S_CD2))[hq * 64 + rA] = d2;
            ((int*)  (sm + S_CK1))[hq * 64 + rA] = k1;
            ((int*)  (sm + S_CK2))[hq * 64 + rA] = k2;
            ((float*)(sm + S_CD1))[hq * 64 + rB] = d1b;
            ((float*)(sm + S_CD2))[hq * 64 + rB] = d2b;
            ((int*)  (sm + S_CK1))[hq * 64 + rB] = k1b;
            ((int*)  (sm + S_CK2))[hq * 64 + rB] = k2b;
        }
        __syncthreads();

        // ---- one thread per row: merge quarters (index order), fixup ------
        float rowmin = 0.f;
        if (t < 64) {
            const float* cd1 = (const float*)(sm + S_CD1);
            const float* cd2 = (const float*)(sm + S_CD2);
            const int*   ck1 = (const int*)(sm + S_CK1);
            const int*   ck2 = (const int*)(sm + S_CK2);
            float m1 = cd1[t], m2 = cd2[t];
            int   q1 = ck1[t], q2 = ck2[t];
#pragma unroll
            for (int qq = 1; qq < 4; ++qq)
                top2_merge(cd1[qq * 64 + t], ck1[qq * 64 + t],
                           cd2[qq * 64 + t], ck2[qq * 64 + t],
                           m1, q1, m2, q2);
            const float xr2 = xxp[t] + xxp[64 + t] + xxp[128 + t] + xxp[192 + t];
            const float TAU = 1e-5f;
            if (m2 - m1 < TAU) {   // exact fp32 recompute, full domain
                const float* xr = x + (size_t)bb * 65536 + hw0 + t;
                const float DA = xr2 + ee[q1] - 2.f * dot_exact(xr, w + (size_t)q1 * 64);
                const float DB = xr2 + ee[q2] - 2.f * dot_exact(xr, w + (size_t)q2 * 64);
                if (DB < DA || (DB == DA && q2 < q1)) { q1 = q2; m1 = DB; }
                else m1 = DA;
            }
            ((int*)(sm + S_IDX))[t] = q1;
            out[OFF_EIDX + n0 + t] = (float)q1;
            rowmin = m1;
            atomicAdd(&g_cnt[q1], 1u);
        }

        // ---- loss partial: rows live in warps 0-1 -------------------------
#pragma unroll
        for (int off = 16; off > 0; off >>= 1)
            rowmin += __shfl_down_sync(0xffffffffu, rowmin, off);
        if (lane == 0 && wid < 2) ((float*)(sm + S_LRED))[wid] = rowmin;
        __syncthreads();
        if (t == 0) {
            const float* lr = (const float*)(sm + S_LRED);
            const float ctaLoss = lr[0] + lr[1];
            atomicAdd(&g_loss_i[bb],
                      (unsigned long long)((double)ctaLoss * 65536.0 + 0.5));
        }

        // ---- encodings: one-hot rows via aligned STG.128 ------------------
        {
            const int* idxs = (const int*)(sm + S_IDX);
#pragma unroll
            for (int rr = 0; rr < 4; ++rr) {
                const int row = wid * 4 + rr;
                const int ebk = idxs[row];
                float* ep = out + OFF_ENC + (size_t)(n0 + row) * 512;
                if (lane < 3)       ep[lane] = (lane == ebk) ? 1.f : 0.f;
                else if (lane == 3) ep[511]  = (511 == ebk) ? 1.f : 0.f;
                const int qhot = (ebk - 3) >> 2;   // quad containing ebk (ebk>=3)
#pragma unroll
                for (int s2 = 0; s2 < 4; ++s2) {
                    const int q = lane + 32 * s2;
                    if (q < 127) {
                        float4 v = make_float4(0.f, 0.f, 0.f, 0.f);
                        if (q == qhot) {
                            const int b = 3 + 4 * q;
                            v.x = (b == ebk);     v.y = (b + 1 == ebk);
                            v.z = (b + 2 == ebk); v.w = (b + 3 == ebk);
                        }
                        *(float4*)(ep + 3 + 4 * q) = v;
                    }
                }
            }
        }

        // ---- q_out via SMEM transpose staging (reuses stage region) -------
        __syncthreads();
        {
            float* qs = (float*)(sm + S_STG);
            const int* idxs = (const int*)(sm + S_IDX);
            const int rr = wid * 4;
#pragma unroll
            for (int q = 0; q < 4; ++q) {
                const float* wr = w + (size_t)idxs[rr + q] * 64;
                qs[(rr + q) * 66 + lane]      = wr[lane];
                qs[(rr + q) * 66 + 32 + lane] = wr[32 + lane];
            }
            __syncthreads();
            float* qb = out + OFF_Q + (size_t)bb * 65536 + hw0;
#pragma unroll
            for (int i2 = 0; i2 < 8; ++i2) {
                const int u = t + 512 * i2;
                const int c = u >> 6, hl = u & 63;
                qb[(size_t)c * 1024 + hl] = qs[hl * 66 + c];
            }
        }
    }

    // ---- last-CTA finalize: perplexity + loss, then reset scratch ---------
    __shared__ unsigned s_last;
    __threadfence();
    __syncthreads();
    if (t == 0) s_last = (atomicAdd(&g_tick, 1u) == gridDim.x - 1) ? 1u : 0u;
    __syncthreads();
    if (s_last) {
        __threadfence();
        const unsigned c0 = *(volatile unsigned*)&g_cnt[t];
        const float p0 = (float)c0 * (1.f / 65536.f);
        float s = p0 * logf(p0 + 1e-10f);
#pragma unroll
        for (int off = 16; off > 0; off >>= 1) s += __shfl_down_sync(0xffffffffu, s, off);
        float* red = (float*)(sm + S_LRED);
        if (lane == 0) red[wid] = s;
        __syncthreads();
        if (t == 0) {
            float tot = 0.f;
#pragma unroll
            for (int q = 0; q < 16; ++q) tot += red[q];
            out[OFF_PERP] = expf(-tot);
        }
        if (t < 64) {
            const unsigned long long v = *(volatile unsigned long long*)&g_loss_i[t];
            out[OFF_LOSS + t] = (float)((double)v * (1.25 / (65536.0 * 65536.0)));
            g_loss_i[t] = 0ull;
        }
        g_cnt[t] = 0u;
        if (t == 0) g_tick = 0u;
    }
}

// ===========================================================================
extern "C" void kernel_launch(void* const* d_in, const int* in_sizes, int n_in,
                              void* d_out, int out_size) {
    const float* x = (const float*)d_in[0];
    const float* w = (const float*)d_in[1];
    float* out = (float*)d_out;

    cudaFuncSetAttribute(k_main, cudaFuncAttributeMaxDynamicSharedMemorySize, S_TOTAL);
    k_main<<<152, 512, S_TOTAL>>>(x, w, out);
}